// round 5
// baseline (speedup 1.0000x reference)
#include <cuda_runtime.h>
#include <math.h>

#define NN     576
#define MR     144
#define RD     15
#define EDGES  (MR * RD)        // 2160
#define BATCH  256
#define ITERS  3
#define CPT    (NN / MR)        // 4 columns owned per thread
#define MAXDEG 18               // column-degree bound (Poisson(3.75) tail: P ~ 0)

#define E_BYTES   (MAXDEG * NN * sizeof(float2))   // 82944
#define V_BYTES   (NN * sizeof(float2))            // 4608
#define F_BYTES   (NN * sizeof(int))               // 2304
#define SMEM_BYTES (E_BYTES + V_BYTES + F_BYTES)   // 89856

// Column indices of the 15 ones in each of the 144 rows of H.
__device__ int g_cols[EDGES];

// Prep: one block per row, 576 threads, one coalesced load each.
__global__ void ldpc_prep(const float* __restrict__ H) {
    __shared__ int woff[18];
    const int m = blockIdx.x;
    const int t = threadIdx.x;
    const int w = t >> 5, l = t & 31;

    const float v = H[m * NN + t];
    const unsigned mask = __ballot_sync(0xFFFFFFFFu, v == 1.0f);
    if (l == 0) woff[w] = __popc(mask);
    __syncthreads();
    if (w == 0) {
        int orig = (l < 18) ? woff[l] : 0;
        int c = orig;
        #pragma unroll
        for (int off = 1; off < 32; off <<= 1) {
            int x = __shfl_up_sync(0xFFFFFFFFu, c, off);
            if (l >= off) c += x;
        }
        if (l < 18) woff[l] = c - orig;   // exclusive prefix
    }
    __syncthreads();
    if (v == 1.0f) {
        int pos = woff[w] + __popc(mask & ((1u << l) - 1u));
        g_cols[m * RD + pos] = t;
    }
}

// Decode: one block = TWO batch elements vectorized in float2 lanes.
// Thread = one check row AND owner of the 4 columns {row + k*144}.
// Rows scatter float2 messages into a transposed column-slot array; columns
// gather+sum conflict-free. No atomics in the iteration loop.
__global__ __launch_bounds__(MR, 1)
void ldpc_decode_kernel(const float* __restrict__ r,
                        const float* __restrict__ alpha,
                        const float* __restrict__ beta,
                        float* __restrict__ out) {
    extern __shared__ char sm[];
    float2* E_sh = (float2*)sm;                       // [MAXDEG*NN]
    float2* V    = (float2*)(sm + E_BYTES);           // [NN]
    int*    fill = (int*)(sm + E_BYTES + V_BYTES);    // [NN]
    int*    cstg = (int*)sm;                          // staging overlays E_sh

    const int row = threadIdx.x;        // 0..143
    const int b0  = blockIdx.x * 2;

    // Coalesced staging of g_cols into shared.
    #pragma unroll
    for (int e = row; e < EDGES; e += MR) cstg[e] = g_cols[e];

    float a_[ITERS], bt_[ITERS];
    #pragma unroll
    for (int it = 0; it < ITERS; it++) { a_[it] = alpha[it]; bt_[it] = beta[it]; }

    // Owned-column channel values for both batch elements; init V and fill.
    float2 rc[CPT];
    #pragma unroll
    for (int k = 0; k < CPT; k++) {
        int n = row + k * MR;
        rc[k].x = r[b0 * NN + n];
        rc[k].y = r[(b0 + 1) * NN + n];
        V[n]    = rc[k];
        fill[n] = 0;
    }
    __syncthreads();   // staging + fill ready

    int cols[RD];
    #pragma unroll
    for (int j = 0; j < RD; j++) cols[j] = cstg[row * RD + j];

    // One-time slot assignment (batch-independent, amortized over 2 elements).
    int slot[RD];
    #pragma unroll
    for (int j = 0; j < RD; j++) {
        int q = atomicAdd(&fill[cols[j]], 1);
        slot[j] = q * NN + cols[j];
    }
    __syncthreads();   // slots done; staging reads done (E_sh region now free)

    int cd[CPT];
    #pragma unroll
    for (int k = 0; k < CPT; k++) cd[k] = fill[row + k * MR];

    float2 Eprev[RD];
    #pragma unroll
    for (int j = 0; j < RD; j++) Eprev[j] = make_float2(0.0f, 0.0f);

    #pragma unroll
    for (int it = 0; it < ITERS; it++) {
        const float a  = a_[it];
        const float bt = bt_[it];

        // ---- row phase: extrinsic msgs, min1/min2/argmin, sign XOR (x2 lanes) ----
        float amx[RD], amy[RD];
        unsigned sbx[RD], sby[RD];
        unsigned sgx = 0u, sgy = 0u;
        #pragma unroll
        for (int j = 0; j < RD; j++) {
            float2 v = V[cols[j]];
            float mx = v.x - Eprev[j].x;
            float my = v.y - Eprev[j].y;
            sbx[j] = __float_as_uint(mx) & 0x80000000u;  sgx ^= sbx[j];
            sby[j] = __float_as_uint(my) & 0x80000000u;  sgy ^= sby[j];
            amx[j] = fabsf(mx);
            amy[j] = fabsf(my);
        }
        // two-chain min1/min2 per lane
        float xa1 = INFINITY, xa2 = INFINITY; int xja = 0;
        float ya1 = INFINITY, ya2 = INFINITY; int yja = 0;
        #pragma unroll
        for (int j = 0; j < 8; j++) {
            if (amx[j] < xa1) { xa2 = xa1; xa1 = amx[j]; xja = j; }
            else if (amx[j] < xa2) { xa2 = amx[j]; }
            if (amy[j] < ya1) { ya2 = ya1; ya1 = amy[j]; yja = j; }
            else if (amy[j] < ya2) { ya2 = amy[j]; }
        }
        float xb1 = INFINITY, xb2 = INFINITY; int xjb = 8;
        float yb1 = INFINITY, yb2 = INFINITY; int yjb = 8;
        #pragma unroll
        for (int j = 8; j < RD; j++) {
            if (amx[j] < xb1) { xb2 = xb1; xb1 = amx[j]; xjb = j; }
            else if (amx[j] < xb2) { xb2 = amx[j]; }
            if (amy[j] < yb1) { yb2 = yb1; yb1 = amy[j]; yjb = j; }
            else if (amy[j] < yb2) { yb2 = amy[j]; }
        }
        const int   xjmin = (xa1 <= xb1) ? xja : xjb;
        const float xmin1 = fminf(xa1, xb1);
        const float xmin2 = (xa1 <= xb1) ? fminf(xa2, xb1) : fminf(xb2, xa1);
        const int   yjmin = (ya1 <= yb1) ? yja : yjb;
        const float ymin1 = fminf(ya1, yb1);
        const float ymin2 = (ya1 <= yb1) ? fminf(ya2, yb1) : fminf(yb2, ya1);

        const float xm1 = a * fmaxf(0.0f, xmin1 - bt);
        const float xm2 = a * fmaxf(0.0f, xmin2 - bt);
        const float ym1 = a * fmaxf(0.0f, ymin1 - bt);
        const float ym2 = a * fmaxf(0.0f, ymin2 - bt);

        #pragma unroll
        for (int j = 0; j < RD; j++) {
            float mgx = (j == xjmin) ? xm2 : xm1;
            float mgy = (j == yjmin) ? ym2 : ym1;
            float2 e;
            e.x = __uint_as_float(__float_as_uint(mgx) ^ (sgx ^ sbx[j]));
            e.y = __uint_as_float(__float_as_uint(mgy) ^ (sgy ^ sby[j]));
            Eprev[j] = e;
            E_sh[slot[j]] = e;
        }
        __syncthreads();   // edges published; V reads done

        // ---- column phase: conflict-free gather-sum of owned columns ----
        if (it < ITERS - 1) {
            #pragma unroll
            for (int k = 0; k < CPT; k++) {
                int n = row + k * MR;
                float2 s = rc[k];
                for (int q = 0; q < cd[k]; q++) {
                    float2 e = E_sh[q * NN + n];
                    s.x += e.x; s.y += e.y;
                }
                V[n] = s;
            }
            __syncthreads();
        } else {
            #pragma unroll
            for (int k = 0; k < CPT; k++) {
                int n = row + k * MR;
                float2 s = rc[k];
                for (int q = 0; q < cd[k]; q++) {
                    float2 e = E_sh[q * NN + n];
                    s.x += e.x; s.y += e.y;
                }
                out[b0 * NN + n]       = s.x;   // coalesced per element
                out[(b0 + 1) * NN + n] = s.y;
            }
        }
    }
}

extern "C" void kernel_launch(void* const* d_in, const int* in_sizes, int n_in,
                              void* d_out, int out_size) {
    const float* r     = (const float*)d_in[0];   // (256, 576)
    const float* H     = (const float*)d_in[1];   // (144, 576)
    const float* alpha = (const float*)d_in[2];   // (3,)
    const float* beta  = (const float*)d_in[3];   // (3,)
    float* out = (float*)d_out;                   // (256, 576)

    cudaFuncSetAttribute(ldpc_decode_kernel,
                         cudaFuncAttributeMaxDynamicSharedMemorySize, SMEM_BYTES);

    ldpc_prep<<<MR, NN>>>(H);
    ldpc_decode_kernel<<<BATCH / 2, MR, SMEM_BYTES>>>(r, alpha, beta, out);
}

// round 6
// speedup vs baseline: 1.1633x; 1.1633x over previous
#include <cuda_runtime.h>
#include <math.h>

#define NN     576
#define MR     144
#define RD     15
#define EDGES  (MR * RD)        // 2160
#define BATCH  256
#define ITERS  3
#define TPB    288              // 2 threads per check row
#define HEDGE  8                // max edges per half-thread (8 + 7)
#define CPT    2                // columns owned per thread (576/288)
#define MAXDEG 18               // column-degree bound

// Column indices of the 15 ones in each of the 144 rows of H.
__device__ int g_cols[EDGES];

// Prep: one block per row, 576 threads, one coalesced load each.
__global__ void ldpc_prep(const float* __restrict__ H) {
    __shared__ int woff[18];
    const int m = blockIdx.x;
    const int t = threadIdx.x;
    const int w = t >> 5, l = t & 31;

    const float v = H[m * NN + t];
    const unsigned mask = __ballot_sync(0xFFFFFFFFu, v == 1.0f);
    if (l == 0) woff[w] = __popc(mask);
    __syncthreads();
    if (w == 0) {
        int orig = (l < 18) ? woff[l] : 0;
        int c = orig;
        #pragma unroll
        for (int off = 1; off < 32; off <<= 1) {
            int x = __shfl_up_sync(0xFFFFFFFFu, c, off);
            if (l >= off) c += x;
        }
        if (l < 18) woff[l] = c - orig;
    }
    __syncthreads();
    if (v == 1.0f) {
        int pos = woff[w] + __popc(mask & ((1u << l) - 1u));
        g_cols[m * RD + pos] = t;
    }
}

// Decode: one block per batch element, 288 threads = 2 per check row.
// Each half handles 8/7 edges; pair merges min1/min2/argmin/sign via shfl_xor(1).
// Rows scatter messages to a transposed column-slot array; each thread then
// gathers 2 owned columns conflict-free. No atomics in the iteration loop.
__global__ __launch_bounds__(TPB, 2)
void ldpc_decode_kernel(const float* __restrict__ r,
                        const float* __restrict__ alpha,
                        const float* __restrict__ beta,
                        float* __restrict__ out) {
    __shared__ float E_sh[MAXDEG * NN];   // transposed edge messages (41.5 KB)
    __shared__ float V[NN];               // posterior
    __shared__ int   fill[NN];            // fill counters -> degrees

    const int t    = threadIdx.x;
    const int row  = t >> 1;              // 0..143 (pair t, t^1 shares row)
    const int half = t & 1;
    const int b    = blockIdx.x;

    // Stage g_cols coalesced into the E region.
    int* cstg = (int*)E_sh;
    #pragma unroll
    for (int e = t; e < EDGES; e += TPB) cstg[e] = g_cols[e];

    float a_[ITERS], bt_[ITERS];
    #pragma unroll
    for (int it = 0; it < ITERS; it++) { a_[it] = alpha[it]; bt_[it] = beta[it]; }

    // Owned columns: n0 = t, n1 = t + 288 (coalesced everywhere).
    const int n0 = t, n1 = t + TPB;
    const float rc0 = r[b * NN + n0];
    const float rc1 = r[b * NN + n1];
    V[n0] = rc0;  V[n1] = rc1;
    fill[n0] = 0; fill[n1] = 0;
    __syncthreads();   // staging + fill ready

    // This half's edges: j in [j0, j0+ne)
    const int j0 = half * HEDGE;                 // 0 or 8
    const int ne = half ? (RD - HEDGE) : HEDGE;  // 7 or 8

    int cols[HEDGE];
    #pragma unroll
    for (int jj = 0; jj < HEDGE; jj++)
        cols[jj] = (jj < ne) ? cstg[row * RD + j0 + jj] : 0;
    __syncthreads();   // staging reads done; E region free

    // One-time slot assignment (unique slot within each column).
    int slot[HEDGE];
    #pragma unroll
    for (int jj = 0; jj < HEDGE; jj++) {
        if (jj < ne) {
            int q = atomicAdd(&fill[cols[jj]], 1);
            slot[jj] = q * NN + cols[jj];
        }
    }
    __syncthreads();

    const int cd0 = fill[n0], cd1 = fill[n1];

    float Eprev[HEDGE];
    #pragma unroll
    for (int jj = 0; jj < HEDGE; jj++) Eprev[jj] = 0.0f;

    #pragma unroll
    for (int it = 0; it < ITERS; it++) {
        const float a  = a_[it];
        const float bt = bt_[it];

        // ---- row phase (half): gather, sign XOR, min1/min2 over my edges ----
        float am[HEDGE];
        unsigned sb[HEDGE];
        unsigned sgn = 0u;
        #pragma unroll
        for (int jj = 0; jj < HEDGE; jj++) {
            if (jj < ne) {
                float m = V[cols[jj]] - Eprev[jj];
                sb[jj] = __float_as_uint(m) & 0x80000000u;
                sgn   ^= sb[jj];
                am[jj] = fabsf(m);
            } else {
                sb[jj] = 0u;
                am[jj] = INFINITY;
            }
        }
        // two sub-chains of 4 + merge (first-index tie-break)
        float a1 = INFINITY, a2 = INFINITY; int ja = j0;
        #pragma unroll
        for (int jj = 0; jj < 4; jj++) {
            if (am[jj] < a1) { a2 = a1; a1 = am[jj]; ja = j0 + jj; }
            else if (am[jj] < a2) { a2 = am[jj]; }
        }
        float b1 = INFINITY, b2 = INFINITY; int jb = j0 + 4;
        #pragma unroll
        for (int jj = 4; jj < HEDGE; jj++) {
            if (am[jj] < b1) { b2 = b1; b1 = am[jj]; jb = j0 + jj; }
            else if (am[jj] < b2) { b2 = am[jj]; }
        }
        const bool  tA = (a1 <= b1);
        float min1 = tA ? a1 : b1;
        float min2 = tA ? fminf(a2, b1) : fminf(b2, a1);
        int   jmin = tA ? ja : jb;

        // ---- cross-half merge via shfl_xor(1) ----
        const float o1 = __shfl_xor_sync(0xFFFFFFFFu, min1, 1);
        const float o2 = __shfl_xor_sync(0xFFFFFFFFu, min2, 1);
        const int   oj = __shfl_xor_sync(0xFFFFFFFFu, jmin, 1);
        const unsigned osg = __shfl_xor_sync(0xFFFFFFFFu, sgn, 1);
        const unsigned sgc = sgn ^ osg;
        // tie prefers the lower edge index (half 0)
        const bool mine = half ? (min1 < o1) : (min1 <= o1);
        const int   jminc = mine ? jmin : oj;
        const float min1c = mine ? min1 : o1;
        const float min2c = mine ? fminf(min2, o1) : fminf(o2, min1);

        const float mag1 = a * fmaxf(0.0f, min1c - bt);
        const float mag2 = a * fmaxf(0.0f, min2c - bt);

        // ---- emit my edges ----
        #pragma unroll
        for (int jj = 0; jj < HEDGE; jj++) {
            if (jj < ne) {
                float mag = ((j0 + jj) == jminc) ? mag2 : mag1;
                float e = __uint_as_float(__float_as_uint(mag) ^ (sgc ^ sb[jj]));
                Eprev[jj] = e;
                E_sh[slot[jj]] = e;
            }
        }
        __syncthreads();   // edges published; V reads done

        // ---- column phase: 2 owned columns, conflict-free ----
        if (it < ITERS - 1) {
            float s0 = rc0, s1 = rc1;
            for (int q = 0; q < cd0; q++) s0 += E_sh[q * NN + n0];
            for (int q = 0; q < cd1; q++) s1 += E_sh[q * NN + n1];
            V[n0] = s0;
            V[n1] = s1;
            __syncthreads();
        } else {
            float s0 = rc0, s1 = rc1;
            for (int q = 0; q < cd0; q++) s0 += E_sh[q * NN + n0];
            for (int q = 0; q < cd1; q++) s1 += E_sh[q * NN + n1];
            out[b * NN + n0] = s0;   // coalesced
            out[b * NN + n1] = s1;
        }
    }
}

extern "C" void kernel_launch(void* const* d_in, const int* in_sizes, int n_in,
                              void* d_out, int out_size) {
    const float* r     = (const float*)d_in[0];   // (256, 576)
    const float* H     = (const float*)d_in[1];   // (144, 576)
    const float* alpha = (const float*)d_in[2];   // (3,)
    const float* beta  = (const float*)d_in[3];   // (3,)
    float* out = (float*)d_out;                   // (256, 576)

    ldpc_prep<<<MR, NN>>>(H);
    ldpc_decode_kernel<<<BATCH, TPB>>>(r, alpha, beta, out);
}